// round 17
// baseline (speedup 1.0000x reference)
#include <cuda_runtime.h>
#include <cuda_fp16.h>
#include <math.h>
#include <stdint.h>

// ---------------------------------------------------------------------------
// GAT, N=4096, NFEAT=2048, D=256, NCLASS=512, heads 4/4/6, alpha=0.2
// Sparse attention (adjacency ~1% -> neighbor lists).
// Projections via warp-level mma.sync fp16 (m16n8k16) with 2-term split:
//   C = A16*Bh + A16*Bl   (A in fp16, B = Bh+Bl fp16 hi/lo, fp32 accum)
// 64x64 warp tiles (4 warps/CTA) to cut smem crossbar traffic.
// Aggregation gathers fp16 Wh (L2-BW-bound) with fp32 weights/accum.
// ---------------------------------------------------------------------------

#define NNODE 4096
#define MAXN  1024

// Scratch (device globals)
__device__ float  g_Wh[6L * 4096 * 512];                  // projections fp32
__device__ __align__(16) __half g_Wh16[6L * 4096 * 512];  // projections fp16 (agg)
__device__ __align__(16) __half g_A [4096L * 2048];       // A operand fp16
__device__ __align__(16) __half g_Bh[6L * 512 * 1024];    // W^T hi [H][N][K]
__device__ __align__(16) __half g_Bl[6L * 512 * 1024];    // W^T lo
__device__ float g_f1[6 * 4096];
__device__ float g_f2[6 * 4096];
__device__ float g_cm[6 * 512];
#define CMCH 32
__device__ float g_cmp[6L * CMCH * 512];
__device__ int   g_nbr[4096L * MAXN];
__device__ int   g_deg[4096];

__device__ __forceinline__ float eluf(float x) { return x > 0.f ? x : expm1f(x); }

__device__ __forceinline__ uint32_t smem_to_u32(const void* p) {
    uint32_t a;
    asm("{ .reg .u64 t; cvta.to.shared.u64 t, %1; cvt.u32.u64 %0, t; }"
        : "=r"(a) : "l"(p));
    return a;
}
#define CPASYNC16(dst, src) \
    asm volatile("cp.async.cg.shared.global [%0], [%1], 16;" \
        :: "r"((uint32_t)(dst)), "l"(src) : "memory")
#define LDSM4(R0, R1, R2, R3, ADDR) \
    asm volatile("ldmatrix.sync.aligned.m8n8.x4.shared.b16 {%0,%1,%2,%3}, [%4];" \
        : "=r"(R0), "=r"(R1), "=r"(R2), "=r"(R3) : "r"(ADDR))
#define MMAF16(C, A, B0, B1) \
    asm volatile("mma.sync.aligned.m16n8k16.row.col.f32.f16.f16.f32 " \
        "{%0,%1,%2,%3}, {%4,%5,%6,%7}, {%8,%9}, {%0,%1,%2,%3};" \
        : "+f"((C)[0]), "+f"((C)[1]), "+f"((C)[2]), "+f"((C)[3]) \
        : "r"((A)[0]), "r"((A)[1]), "r"((A)[2]), "r"((A)[3]), \
          "r"(B0), "r"(B1))

// --------------------------- neighbor-list build ---------------------------
__global__ __launch_bounds__(256) void build_nbr_k(const float* __restrict__ adj) {
    int warp = (blockIdx.x * blockDim.x + threadIdx.x) >> 5;
    int lane = threadIdx.x & 31;
    if (warp >= NNODE) return;
    const float* row = adj + (long)warp * NNODE;
    int* dst = g_nbr + (long)warp * MAXN;
    int base = 0;
    for (int j0 = 0; j0 < NNODE; j0 += 32) {
        float v = row[j0 + lane];
        unsigned m = __ballot_sync(0xffffffffu, v > 0.f);
        if (v > 0.f) {
            int pos = base + __popc(m & ((1u << lane) - 1u));
            if (pos < MAXN) dst[pos] = j0 + lane;
        }
        base += __popc(m);
    }
    if (lane == 0) g_deg[warp] = min(base, MAXN);
}

// ------------------------------ fp32 -> fp16 -------------------------------
__global__ __launch_bounds__(256) void conv_x_k(const float* __restrict__ x, long n) {
    long i = (long)blockIdx.x * blockDim.x + threadIdx.x;
    long stride = (long)gridDim.x * blockDim.x;
    for (; i < n; i += stride) g_A[i] = __float2half_rn(x[i]);
}

// W [H][K][N] fp32 -> Bh/Bl [H][N][K] fp16 hi/lo (32x32 smem-tile transpose)
__global__ __launch_bounds__(256) void wsplit_k(const float* __restrict__ W, int K, int N) {
    __shared__ float tile[32][33];
    int h = blockIdx.z;
    int k0 = blockIdx.x * 32, n0 = blockIdx.y * 32;
    int tx = threadIdx.x & 31, ty = threadIdx.x >> 5;   // 32 x 8
    const float* Wp = W + (long)h * K * N;
#pragma unroll
    for (int i = 0; i < 4; i++)
        tile[ty + i * 8][tx] = Wp[(long)(k0 + ty + i * 8) * N + n0 + tx];
    __syncthreads();
#pragma unroll
    for (int i = 0; i < 4; i++) {
        int n = n0 + ty + i * 8, k = k0 + tx;
        float v = tile[tx][ty + i * 8];
        __half hv = __float2half_rn(v);
        long o = ((long)h * N + n) * K + k;
        g_Bh[o] = hv;
        g_Bl[o] = __float2half_rn(v - __half2float(hv));
    }
}

// -------------------- warp-MMA GEMM (fp16 2-term split) --------------------
// C[h] = A @ B[h]^T; A: [4096,K] fp16; B hi/lo: [H][N][K] fp16 (K-major)
// C: [H][4096][N] fp32 + fp16 copy. CTA tile 128x128, 4 warps (2x2),
// warp tile 64x64. K-chunk 32; 2-stage cp.async pipeline.
#define KC 32
#define PB 40                         // smem row pitch in fp16 (80 B)
#define TILE_BYTES_S (128 * PB * 2)   // one operand tile: 10240 B
#define STAGE_BYTES (3 * TILE_BYTES_S)// A/Bh/Bl: 30720 B
#define GEMM_SMEM (2 * STAGE_BYTES)   // 61440 B

__global__ void __launch_bounds__(128, 2) mma_gemm_k(
    const __half* __restrict__ A,
    const __half* __restrict__ Bh, const __half* __restrict__ Bl,
    float* __restrict__ C, __half* __restrict__ C16, int K, int N)
{
    extern __shared__ __align__(16) char dsm[];
    const uint32_t base = smem_to_u32(dsm);

    const int tid = threadIdx.x, lane = tid & 31, wid = tid >> 5;
    const int m0 = blockIdx.y * 128, n0 = blockIdx.x * 128, h = blockIdx.z;
    const int wm = (wid & 1) * 64;        // warp m offset
    const int wn = (wid >> 1) * 64;       // warp n offset

    // ---- global->smem: one 80B-pitch row per thread per array (4x16B)
    const uint32_t drow = (uint32_t)tid * 80u;
    const __half* pA  = A  + (long)(m0 + tid) * K;
    const __half* pBh = Bh + ((long)h * N + n0 + tid) * K;
    const __half* pBl = Bl + ((long)h * N + n0 + tid) * K;

    // ---- ldmatrix lane address offsets (bytes, within one operand tile)
    const uint32_t aoff = (uint32_t)(wm + (lane & 15)) * 80u + (uint32_t)(lane >> 4) * 16u;
    const uint32_t boff = (uint32_t)(wn + (lane & 7) + ((lane >> 4) << 3)) * 80u
                        + (uint32_t)((lane >> 3) & 1) * 16u;

    float acc[4][8][4];
#pragma unroll
    for (int i = 0; i < 4; i++)
#pragma unroll
        for (int j = 0; j < 8; j++)
#pragma unroll
            for (int q = 0; q < 4; q++) acc[i][j][q] = 0.f;

    const int nk = K / KC;

#define ISSUE_STAGE(T) do {                                              \
        const uint32_t sb = base + ((T) & 1) * STAGE_BYTES;              \
        const long ko = (long)(T) * KC;                                  \
        _Pragma("unroll")                                                \
        for (int s = 0; s < 4; s++) {                                    \
            CPASYNC16(sb + drow + s * 16u, pA + ko + s * 8);             \
            CPASYNC16(sb + TILE_BYTES_S + drow + s * 16u, pBh + ko + s * 8); \
            CPASYNC16(sb + 2 * TILE_BYTES_S + drow + s * 16u, pBl + ko + s * 8); \
        }                                                                \
        asm volatile("cp.async.commit_group;" ::: "memory");             \
    } while (0)

    ISSUE_STAGE(0);

    for (int t = 0; t < nk; t++) {
        if (t + 1 < nk) {
            ISSUE_STAGE(t + 1);
            asm volatile("cp.async.wait_group 1;" ::: "memory");
        } else {
            asm volatile("cp.async.wait_group 0;" ::: "memory");
        }
        __syncthreads();

        const uint32_t sb  = base + (t & 1) * STAGE_BYTES;
        const uint32_t uA  = sb;
        const uint32_t uBh = sb + TILE_BYTES_S;
        const uint32_t uBl = sb + 2 * TILE_BYTES_S;

#pragma unroll
        for (int kk = 0; kk < 2; kk++) {
            const uint32_t kb = kk * 32;    // 16 fp16 = 32 bytes
            uint32_t af[4][4], b[4][4];
            // A fragments (m64 x k16)
#pragma unroll
            for (int ma = 0; ma < 4; ma++)
                LDSM4(af[ma][0], af[ma][1], af[ma][2], af[ma][3],
                      uA + aoff + ma * 1280u + kb);
            // B-hi fragments (n64 x k16)
#pragma unroll
            for (int g = 0; g < 4; g++)
                LDSM4(b[g][0], b[g][1], b[g][2], b[g][3],
                      uBh + boff + g * 1280u + kb);
            // term 1: A*Bh (32 independent accumulators)
#pragma unroll
            for (int ma = 0; ma < 4; ma++)
#pragma unroll
                for (int na = 0; na < 8; na++) {
                    const int g = na >> 1, p = (na & 1) * 2;
                    MMAF16(acc[ma][na], af[ma], b[g][p], b[g][p + 1]);
                }
            // B-lo over b, term 2: A*Bl
#pragma unroll
            for (int g = 0; g < 4; g++)
                LDSM4(b[g][0], b[g][1], b[g][2], b[g][3],
                      uBl + boff + g * 1280u + kb);
#pragma unroll
            for (int ma = 0; ma < 4; ma++)
#pragma unroll
                for (int na = 0; na < 8; na++) {
                    const int g = na >> 1, p = (na & 1) * 2;
                    MMAF16(acc[ma][na], af[ma], b[g][p], b[g][p + 1]);
                }
        }
        __syncthreads();
    }
#undef ISSUE_STAGE

    // ---- epilogue: fp32 C + fp16 C16
    float*  Cf = C   + (long)h * NNODE * N;
    __half* Cg = C16 + (long)h * NNODE * N;
#pragma unroll
    for (int ma = 0; ma < 4; ma++) {
        const int row = m0 + wm + ma * 16 + (lane >> 2);
#pragma unroll
        for (int na = 0; na < 8; na++) {
            const int col = n0 + wn + na * 8 + (lane & 3) * 2;
            float* p = Cf + (long)row * N + col;
            *(float2*)p            = make_float2(acc[ma][na][0], acc[ma][na][1]);
            *(float2*)(p + 8L * N) = make_float2(acc[ma][na][2], acc[ma][na][3]);
            __half* q = Cg + (long)row * N + col;
            *(__half2*)q            = __floats2half2_rn(acc[ma][na][0], acc[ma][na][1]);
            *(__half2*)(q + 8L * N) = __floats2half2_rn(acc[ma][na][2], acc[ma][na][3]);
        }
    }
}

// --------------------------- f1/f2 projections ----------------------------
__global__ __launch_bounds__(256) void f12_k(
    const float* __restrict__ Wh, const float* __restrict__ a, int D)
{
    int lane = threadIdx.x & 31;
    int n = (blockIdx.x * blockDim.x + threadIdx.x) >> 5;
    int h = blockIdx.y;
    if (n >= NNODE) return;
    const float* w  = Wh + ((long)h * NNODE + n) * D;
    const float* ah = a + h * 2 * D;
    float s1 = 0.f, s2 = 0.f;
    for (int d = lane; d < D; d += 32) {
        float v = w[d];
        s1 = fmaf(v, ah[d], s1);
        s2 = fmaf(v, ah[D + d], s2);
    }
    for (int off = 16; off; off >>= 1) {
        s1 += __shfl_down_sync(0xffffffffu, s1, off);
        s2 += __shfl_down_sync(0xffffffffu, s2, off);
    }
    if (lane == 0) { g_f1[h * NNODE + n] = s1; g_f2[h * NNODE + n] = s2; }
}

// column mean of Wh per head (deg==0 fallback) — two-stage reduction
__global__ __launch_bounds__(256) void colmean1_k(const float* __restrict__ Wh, int D)
{
    int chunk = blockIdx.x, h = blockIdx.y;
    const int per = NNODE / CMCH;
    const float* base = Wh + (long)h * NNODE * D + (long)chunk * per * D;
    for (int d = threadIdx.x; d < D; d += 256) {
        float s = 0.f;
        for (int n = 0; n < per; n++) s += base[(long)n * D + d];
        g_cmp[((long)h * CMCH + chunk) * D + d] = s;
    }
}
__global__ __launch_bounds__(256) void colmean2_k(int D)
{
    int d = blockIdx.x * blockDim.x + threadIdx.x;
    int h = blockIdx.y;
    if (d >= D) return;
    float s = 0.f;
    const float* p = g_cmp + (long)h * CMCH * D + d;
    for (int c = 0; c < CMCH; c++) s += p[(long)c * D];
    g_cm[h * D + d] = s * (1.f / NNODE);
}

// ------------------- sparse softmax + aggregate (concat) -------------------
// Gathers fp16 Wh, fp32 weights/accum; writes next layer's fp16 A operand.
__global__ __launch_bounds__(256) void agg_concat_k(
    const __half* __restrict__ Wh16, int H)
{
    const int D = 256;
    int i = blockIdx.x, h = blockIdx.y, t = threadIdx.x;
    __shared__ float sw[MAXN];
    __shared__ int   snb[MAXN];
    __shared__ float red[256];
    int dg = g_deg[i];
    const int* nb = g_nbr + (long)i * MAXN;
    float f1i = g_f1[h * NNODE + i];
    float lmax = -3.4e38f;
    for (int jj = t; jj < dg; jj += 256) {
        int j = nb[jj];
        snb[jj] = j;
        float e = f1i + g_f2[h * NNODE + j];
        e = e >= 0.f ? e : 0.2f * e;          // leaky_relu(alpha=0.2)
        sw[jj] = e;
        lmax = fmaxf(lmax, e);
    }
    red[t] = lmax; __syncthreads();
    for (int s = 128; s > 0; s >>= 1) { if (t < s) red[t] = fmaxf(red[t], red[t + s]); __syncthreads(); }
    float m = red[0]; __syncthreads();
    float lsum = 0.f;
    for (int jj = t; jj < dg; jj += 256) { float w = expf(sw[jj] - m); sw[jj] = w; lsum += w; }
    red[t] = lsum; __syncthreads();
    for (int s = 128; s > 0; s >>= 1) { if (t < s) red[t] += red[t + s]; __syncthreads(); }
    float inv = 1.f / red[0]; __syncthreads();

    float acc;
    if (dg > 0) {
        const __half* whh = Wh16 + (long)h * NNODE * D;
        float a0 = 0.f, a1 = 0.f, a2 = 0.f, a3 = 0.f;
        int jj = 0;
        for (; jj + 4 <= dg; jj += 4) {
            a0 = fmaf(sw[jj + 0], __half2float((whh + (long)snb[jj + 0] * D)[t]), a0);
            a1 = fmaf(sw[jj + 1], __half2float((whh + (long)snb[jj + 1] * D)[t]), a1);
            a2 = fmaf(sw[jj + 2], __half2float((whh + (long)snb[jj + 2] * D)[t]), a2);
            a3 = fmaf(sw[jj + 3], __half2float((whh + (long)snb[jj + 3] * D)[t]), a3);
        }
        for (; jj < dg; jj++)
            a0 = fmaf(sw[jj], __half2float((whh + (long)snb[jj] * D)[t]), a0);
        acc = ((a0 + a1) + (a2 + a3)) * inv;
    } else {
        acc = g_cm[h * D + t];                // uniform softmax over all nodes
    }
    acc = eluf(eluf(acc));                    // reference applies elu twice
    g_A[(long)i * (H * D) + h * D + t] = __float2half_rn(acc);
}

// ------------- output layer: 6 heads, mean, elu, L2-normalize -------------
// Thread t handles cols 2t, 2t+1 (half2 gather loads).
__global__ __launch_bounds__(256) void agg_mean_norm_k(
    const __half* __restrict__ Wh16, float* __restrict__ out)
{
    const int D = 512;
    int i = blockIdx.x, t = threadIdx.x;
    __shared__ float sw[MAXN];
    __shared__ int   snb[MAXN];
    __shared__ float red[256];
    int dg = g_deg[i];
    const int* nb = g_nbr + (long)i * MAXN;
    for (int jj = t; jj < dg; jj += 256) snb[jj] = nb[jj];
    __syncthreads();

    float acc0 = 0.f, acc1 = 0.f;
    for (int h = 0; h < 6; h++) {
        float f1i = g_f1[h * NNODE + i];
        float lmax = -3.4e38f;
        for (int jj = t; jj < dg; jj += 256) {
            float e = f1i + g_f2[h * NNODE + snb[jj]];
            e = e >= 0.f ? e : 0.2f * e;
            sw[jj] = e;
            lmax = fmaxf(lmax, e);
        }
        red[t] = lmax; __syncthreads();
        for (int s = 128; s > 0; s >>= 1) { if (t < s) red[t] = fmaxf(red[t], red[t + s]); __syncthreads(); }
        float m = red[0]; __syncthreads();
        float lsum = 0.f;
        for (int jj = t; jj < dg; jj += 256) { float w = expf(sw[jj] - m); sw[jj] = w; lsum += w; }
        red[t] = lsum; __syncthreads();
        for (int s = 128; s > 0; s >>= 1) { if (t < s) red[t] += red[t + s]; __syncthreads(); }
        float inv = 1.f / red[0]; __syncthreads();

        if (dg > 0) {
            const __half2* whh = (const __half2*)(Wh16 + (long)h * NNODE * D);
            float a0 = 0.f, a1 = 0.f, b0 = 0.f, b1 = 0.f;
            int jj = 0;
            for (; jj + 2 <= dg; jj += 2) {
                float2 fa = __half22float2(whh[(long)snb[jj]     * 256 + t]);
                float2 fb = __half22float2(whh[(long)snb[jj + 1] * 256 + t]);
                float wa = sw[jj], wb = sw[jj + 1];
                a0 = fmaf(wa, fa.x, a0);
                a1 = fmaf(wa, fa.y, a1);
                b0 = fmaf(wb, fb.x, b0);
                b1 = fmaf(wb, fb.y, b1);
            }
            if (jj < dg) {
                float2 fa = __half22float2(whh[(long)snb[jj] * 256 + t]);
                float wa = sw[jj];
                a0 = fmaf(wa, fa.x, a0);
                a1 = fmaf(wa, fa.y, a1);
            }
            acc0 += (a0 + b0) * inv;
            acc1 += (a1 + b1) * inv;
        } else {
            acc0 += g_cm[h * D + 2 * t];
            acc1 += g_cm[h * D + 2 * t + 1];
        }
        __syncthreads();   // sw reused next head
    }
    acc0 *= (1.f / 6.f); acc1 *= (1.f / 6.f);
    acc0 = eluf(acc0);   acc1 = eluf(acc1);
    red[t] = acc0 * acc0 + acc1 * acc1; __syncthreads();
    for (int s = 128; s > 0; s >>= 1) { if (t < s) red[t] += red[t + s]; __syncthreads(); }
    float nrm = sqrtf(red[0]);
    float inv2 = 1.f / fmaxf(nrm, 1e-12f);
    *(float2*)(out + (long)i * D + 2 * t) = make_float2(acc0 * inv2, acc1 * inv2);
}

// ------------------------------- launcher ----------------------------------
extern "C" void kernel_launch(void* const* d_in, const int* in_sizes, int n_in,
                              void* d_out, int out_size) {
    const float* x   = (const float*)d_in[0];   // [4096, 2048]
    const float* adj = (const float*)d_in[1];   // [4096, 4096]
    const float* W1  = (const float*)d_in[2];   // [4, 2048, 256]
    const float* a1  = (const float*)d_in[3];   // [4, 512]
    const float* W2  = (const float*)d_in[4];   // [4, 1024, 256]
    const float* a2  = (const float*)d_in[5];   // [4, 512]
    const float* W3  = (const float*)d_in[6];   // [6, 1024, 512]
    const float* a3  = (const float*)d_in[7];   // [6, 1024]
    float* out = (float*)d_out;                 // [4096, 512]

    static int attr_set = 0;
    if (!attr_set) {
        cudaFuncSetAttribute(mma_gemm_k,
                             cudaFuncAttributeMaxDynamicSharedMemorySize, GEMM_SMEM);
        attr_set = 1;
    }

    float* pWh = nullptr;
    __half *pWh16 = nullptr, *pA = nullptr, *pBh = nullptr, *pBl = nullptr;
    cudaGetSymbolAddress((void**)&pWh, g_Wh);
    cudaGetSymbolAddress((void**)&pWh16, g_Wh16);
    cudaGetSymbolAddress((void**)&pA, g_A);
    cudaGetSymbolAddress((void**)&pBh, g_Bh);
    cudaGetSymbolAddress((void**)&pBl, g_Bl);

    build_nbr_k<<<512, 256>>>(adj);

    // ---- layer 1: H=4, K=2048, N(out)=256 ----
    conv_x_k<<<4096, 256>>>(x, 4096L * 2048);
    wsplit_k<<<dim3(64, 8, 4), 256>>>(W1, 2048, 256);
    mma_gemm_k<<<dim3(2, 32, 4), 128, GEMM_SMEM>>>(pA, pBh, pBl, pWh, pWh16, 2048, 256);
    f12_k<<<dim3(512, 4), 256>>>(pWh, a1, 256);
    colmean1_k<<<dim3(CMCH, 4), 256>>>(pWh, 256);
    colmean2_k<<<dim3(1, 4), 256>>>(256);
    agg_concat_k<<<dim3(NNODE, 4), 256>>>(pWh16, 4);   // writes g_A [4096,1024] fp16

    // ---- layer 2: H=4, K=1024, N(out)=256 ----
    wsplit_k<<<dim3(32, 8, 4), 256>>>(W2, 1024, 256);
    mma_gemm_k<<<dim3(2, 32, 4), 128, GEMM_SMEM>>>(pA, pBh, pBl, pWh, pWh16, 1024, 256);
    f12_k<<<dim3(512, 4), 256>>>(pWh, a2, 256);
    colmean1_k<<<dim3(CMCH, 4), 256>>>(pWh, 256);
    colmean2_k<<<dim3(1, 4), 256>>>(256);
    agg_concat_k<<<dim3(NNODE, 4), 256>>>(pWh16, 4);   // writes g_A [4096,1024] fp16

    // ---- output layer: H=6, K=1024, N(out)=512, mean+elu+normalize ----
    wsplit_k<<<dim3(32, 16, 6), 256>>>(W3, 1024, 512);
    mma_gemm_k<<<dim3(4, 32, 6), 128, GEMM_SMEM>>>(pA, pBh, pBl, pWh, pWh16, 1024, 512);
    f12_k<<<dim3(512, 6), 256>>>(pWh, a3, 512);
    colmean1_k<<<dim3(CMCH, 6), 256>>>(pWh, 512);
    colmean2_k<<<dim3(2, 6), 256>>>(512);
    agg_mean_norm_k<<<NNODE, 256>>>(pWh16, out);
}